// round 3
// baseline (speedup 1.0000x reference)
#include <cuda_runtime.h>
#include <math.h>

#define B_    32
#define INC_  10
#define LIN_  16384
#define CH_   20
#define NPOLY 12
#define MM_   6
#define NB_   4
// lengths: l0=16434, each block shrinks by 12 -> 16422,16410,16398,16386

#define BUFN 10520000  // >= 32*20*16434

__device__ float g_xa[BUFN];
__device__ float g_xb[BUFN];
__device__ float g_y2[BUFN];

__device__ __forceinline__ float gelu_f(float x) {
    return 0.5f * x * (1.0f + erff(x * 0.7071067811865476f));
}

// ---------------------------------------------------------------------------
// First conv: input (B,10,16384) wrap-padded (25,27), conv3 -> (B,20,16434)
// ---------------------------------------------------------------------------
__global__ void __launch_bounds__(128) k_first(
    const float* __restrict__ in, const float* __restrict__ w,
    float* __restrict__ out, int lout)
{
    __shared__ float sw[CH_ * INC_ * 3];
    int tid = threadIdx.x;
    for (int i = tid; i < CH_ * INC_ * 3; i += blockDim.x) sw[i] = w[i];
    __syncthreads();

    int b = blockIdx.y;
    int t = blockIdx.x * blockDim.x + tid;
    if (t >= lout) return;

    int base = t - 25;
    int i0 = base;     if (i0 < 0) i0 += LIN_; else if (i0 >= LIN_) i0 -= LIN_;
    int i1 = base + 1; if (i1 < 0) i1 += LIN_; else if (i1 >= LIN_) i1 -= LIN_;
    int i2 = base + 2; if (i2 < 0) i2 += LIN_; else if (i2 >= LIN_) i2 -= LIN_;

    const float* inb = in + (size_t)b * INC_ * LIN_;
    float acc[CH_];
#pragma unroll
    for (int co = 0; co < CH_; co++) acc[co] = 0.f;
#pragma unroll
    for (int ci = 0; ci < INC_; ci++) {
        float v0 = inb[ci * LIN_ + i0];
        float v1 = inb[ci * LIN_ + i1];
        float v2 = inb[ci * LIN_ + i2];
#pragma unroll
        for (int co = 0; co < CH_; co++) {
            const float* wp = sw + (co * INC_ + ci) * 3;
            acc[co] = fmaf(wp[0], v0, fmaf(wp[1], v1, fmaf(wp[2], v2, acc[co])));
        }
    }
    float* ob = out + (size_t)b * CH_ * lout;
#pragma unroll
    for (int co = 0; co < CH_; co++) ob[co * lout + t] = acc[co];
}

// ---------------------------------------------------------------------------
// Fused conv_a -> gelu -> conv_b. Tile: NTC y2-outputs.
// 4 warps x (5 output channels each); positions strided by 32 within tile.
// ---------------------------------------------------------------------------
#define NTC 256
#define XROW 292   // >= 260 needed; slack so v=8 speculative reads stay in-row
#define YROW 258

__global__ void __launch_bounds__(128) k_convAB(
    const float* __restrict__ x, const float* __restrict__ wa,
    const float* __restrict__ wb, float* __restrict__ y2, int l)
{
    __shared__ float xs[CH_][XROW];
    __shared__ float y1s[CH_][YROW];
    __shared__ float swa[CH_ * CH_ * 3];
    __shared__ float swb[CH_ * CH_ * 3];

    int tid = threadIdx.x;
    int b = blockIdx.y;
    int T0 = blockIdx.x * NTC;
    int l2 = l - 4;

    for (int i = tid; i < CH_ * CH_ * 3; i += 128) { swa[i] = wa[i]; swb[i] = wb[i]; }
    for (int i = tid; i < CH_ * 260; i += 128) {
        int ci = i / 260, j = i % 260;
        int gp = T0 + j;
        xs[ci][j] = (gp < l) ? x[((size_t)b * CH_ + ci) * l + gp] : 0.f;
    }
    __syncthreads();

    int w = tid >> 5, lane = tid & 31;
    int cob = 5 * w;

    // Stage B: y1[j] = gelu(conv_a(x)[j]), j = lane + 32v, v<9, j<258
    {
        float a[5][9];
#pragma unroll
        for (int cc = 0; cc < 5; cc++)
#pragma unroll
            for (int v = 0; v < 9; v++) a[cc][v] = 0.f;

#pragma unroll
        for (int ci = 0; ci < CH_; ci++) {
            float wr[15];
#pragma unroll
            for (int cc = 0; cc < 5; cc++)
#pragma unroll
                for (int k = 0; k < 3; k++)
                    wr[cc * 3 + k] = swa[((cob + cc) * CH_ + ci) * 3 + k];
#pragma unroll
            for (int v = 0; v < 9; v++) {
                int j = lane + 32 * v;
                float x0 = xs[ci][j], x1 = xs[ci][j + 1], x2 = xs[ci][j + 2];
#pragma unroll
                for (int cc = 0; cc < 5; cc++)
                    a[cc][v] = fmaf(wr[cc * 3], x0,
                               fmaf(wr[cc * 3 + 1], x1,
                               fmaf(wr[cc * 3 + 2], x2, a[cc][v])));
            }
        }
#pragma unroll
        for (int v = 0; v < 9; v++) {
            int j = lane + 32 * v;
            if (j < YROW) {
#pragma unroll
                for (int cc = 0; cc < 5; cc++) y1s[cob + cc][j] = gelu_f(a[cc][v]);
            }
        }
    }
    __syncthreads();

    // Stage C: y2[t] = conv_b(y1)[t], t = T0 + lane + 32v, v<8
    {
        float a[5][8];
#pragma unroll
        for (int cc = 0; cc < 5; cc++)
#pragma unroll
            for (int v = 0; v < 8; v++) a[cc][v] = 0.f;

#pragma unroll
        for (int ci = 0; ci < CH_; ci++) {
            float wr[15];
#pragma unroll
            for (int cc = 0; cc < 5; cc++)
#pragma unroll
                for (int k = 0; k < 3; k++)
                    wr[cc * 3 + k] = swb[((cob + cc) * CH_ + ci) * 3 + k];
#pragma unroll
            for (int v = 0; v < 8; v++) {
                int j = lane + 32 * v;
                float x0 = y1s[ci][j], x1 = y1s[ci][j + 1], x2 = y1s[ci][j + 2];
#pragma unroll
                for (int cc = 0; cc < 5; cc++)
                    a[cc][v] = fmaf(wr[cc * 3], x0,
                               fmaf(wr[cc * 3 + 1], x1,
                               fmaf(wr[cc * 3 + 2], x2, a[cc][v])));
            }
        }
#pragma unroll
        for (int v = 0; v < 8; v++) {
            int t = T0 + lane + 32 * v;
            if (t < l2) {
#pragma unroll
                for (int cc = 0; cc < 5; cc++)
                    y2[((size_t)b * CH_ + cob + cc) * l2 + t] = a[cc][v];
            }
        }
    }
}

// ---------------------------------------------------------------------------
// Fused Legendre decompose + block-diag mix + overlap-add recon + residual + gelu.
// Flat mode-major axis q = mi*20+ci. Group g mixes q in [6g,6g+6).
//   v[q,tau] = sum_k (fd[mi,k]/2) * x[b, ci, 6tau+k]
//   u[p,tau] = sum_i lm[g, p%6, i] * v[6g+i, tau]
//   rec[co,t]: pglob=t+6, t0=pglob/6, k0=pglob%6:
//     rec = sum_mo u[mo*20+co, t0]*fr[mo,k0] + u[mo*20+co, t0-1]*fr[mo,k0+6]
//   out = gelu(rec + y2[t+4])
// Tile: NTO=384 outputs -> tau in [T0/6, T0/6+64] (65 values).
// ---------------------------------------------------------------------------
#define NTO 384
#define NTAU 65
#define XR 401   // >= 396; odd to dodge bank conflicts across rows

__global__ void __launch_bounds__(256) k_legrec(
    const float* __restrict__ x, const float* __restrict__ lm_g,
    const float* __restrict__ fd, const float* __restrict__ fr,
    const float* __restrict__ y2, float* __restrict__ out,
    int l, int lo)
{
    __shared__ float xs[CH_][XR];
    __shared__ float u[120][NTAU + 1];
    __shared__ float fd2[MM_ * NPOLY];
    __shared__ float sfr[MM_ * NPOLY];
    __shared__ float lm[CH_ * MM_ * MM_];

    int tid = threadIdx.x;
    int b = blockIdx.y;
    int T0 = blockIdx.x * NTO;
    int tau0 = T0 / 6;

    for (int i = tid; i < MM_ * NPOLY; i += 256) { fd2[i] = 0.5f * fd[i]; sfr[i] = fr[i]; }
    for (int i = tid; i < CH_ * MM_ * MM_; i += 256) lm[i] = lm_g[i];
    for (int i = tid; i < CH_ * 396; i += 256) {
        int ci = i / 396, j = i % 396;
        int gp = 6 * tau0 + j;
        xs[ci][j] = (gp < l) ? x[((size_t)b * CH_ + ci) * l + gp] : 0.f;
    }
    __syncthreads();

    // Stage 2: v (regs) -> u (smem). Tasks: (g, s), 20*65 = 1300.
    for (int task = tid; task < CH_ * NTAU; task += 256) {
        int g = task % CH_;
        int s = task / CH_;
        float v[MM_];
#pragma unroll
        for (int i = 0; i < MM_; i++) {
            int q = 6 * g + i;
            int mi = q / CH_;
            int ci = q % CH_;
            float acc = 0.f;
#pragma unroll
            for (int k = 0; k < NPOLY; k++)
                acc = fmaf(fd2[mi * NPOLY + k], xs[ci][6 * s + k], acc);
            v[i] = acc;
        }
#pragma unroll
        for (int o = 0; o < MM_; o++) {
            float acc = 0.f;
#pragma unroll
            for (int i = 0; i < MM_; i++)
                acc = fmaf(lm[(g * MM_ + o) * MM_ + i], v[i], acc);
            u[6 * g + o][s] = acc;
        }
    }
    __syncthreads();

    // Stage 3: reconstruct + residual + gelu. Tasks: (co, tloc), 20*384.
    int l2row = lo + 8;
    for (int task = tid; task < CH_ * NTO; task += 256) {
        int co = task / NTO;
        int tloc = task % NTO;
        int t = T0 + tloc;
        if (t >= lo) continue;

        int pg = t + 6;
        int t0 = pg / 6;
        int k0 = pg - 6 * t0;
        int s = t0 - tau0;   // in [1, 64]

        float acc = 0.f;
#pragma unroll
        for (int mo = 0; mo < MM_; mo++) {
            int pp = mo * CH_ + co;
            acc = fmaf(u[pp][s],     sfr[mo * NPOLY + k0],     acc);
            acc = fmaf(u[pp][s - 1], sfr[mo * NPOLY + k0 + 6], acc);
        }
        float val = acc + y2[((size_t)b * CH_ + co) * l2row + t + 4];
        out[((size_t)b * CH_ + co) * lo + t] = gelu_f(val);
    }
}

// ---------------------------------------------------------------------------
// Final: out[b,t] = sum_o w_out[o] * gelu(sum_c w11[o,c]*x[b,c,t]), VT=2
// ---------------------------------------------------------------------------
__global__ void __launch_bounds__(128) k_final(
    const float* __restrict__ x, const float* __restrict__ w11,
    const float* __restrict__ w_out, float* __restrict__ out, int lin)
{
    __shared__ float sw[128 * CH_];
    __shared__ float so[128];
    int tid = threadIdx.x;
    for (int i = tid; i < 128 * CH_; i += blockDim.x) sw[i] = w11[i];
    if (tid < 128) so[tid] = w_out[tid];
    __syncthreads();

    int b = blockIdx.y;
    int t0 = (blockIdx.x * blockDim.x + tid) * 2;
    if (t0 >= LIN_) return;

    const float* xb = x + (size_t)b * CH_ * lin + t0;
    float xv0[CH_], xv1[CH_];
#pragma unroll
    for (int c = 0; c < CH_; c++) { xv0[c] = xb[c * lin]; xv1[c] = xb[c * lin + 1]; }

    float acc0 = 0.f, acc1 = 0.f;
#pragma unroll 4
    for (int o = 0; o < 128; o++) {
        float h0 = 0.f, h1 = 0.f;
#pragma unroll
        for (int c = 0; c < CH_; c++) {
            float wv = sw[o * CH_ + c];
            h0 = fmaf(wv, xv0[c], h0);
            h1 = fmaf(wv, xv1[c], h1);
        }
        float ov = so[o];
        acc0 = fmaf(ov, gelu_f(h0), acc0);
        acc1 = fmaf(ov, gelu_f(h1), acc1);
    }
    out[(size_t)b * LIN_ + t0] = acc0;
    out[(size_t)b * LIN_ + t0 + 1] = acc1;
}

// ---------------------------------------------------------------------------
extern "C" void kernel_launch(void* const* d_in, const int* in_sizes, int n_in,
                              void* d_out, int out_size)
{
    const float* input  = (const float*)d_in[0];
    const float* w_first= (const float*)d_in[1];
    const float* conv_a = (const float*)d_in[2];
    const float* conv_b = (const float*)d_in[3];
    const float* lin_m  = (const float*)d_in[4];
    const float* w11    = (const float*)d_in[5];
    const float* w_out  = (const float*)d_in[6];
    const float* filt_d = (const float*)d_in[7];
    const float* filt_r = (const float*)d_in[8];
    float* out = (float*)d_out;

    float *xa, *xb, *y2;
    cudaGetSymbolAddress((void**)&xa, g_xa);
    cudaGetSymbolAddress((void**)&xb, g_xb);
    cudaGetSymbolAddress((void**)&y2, g_y2);

    int l = 16434;
    {
        dim3 g((l + 127) / 128, B_);
        k_first<<<g, 128>>>(input, w_first, xa, l);
    }

    float* cur = xa;
    float* alt = xb;
    for (int i = 0; i < NB_; i++) {
        int l2 = l - 4;
        int lo = l - 12;

        dim3 gc((l2 + NTC - 1) / NTC, B_);
        k_convAB<<<gc, 128>>>(cur, conv_a + i * CH_ * CH_ * 3,
                              conv_b + i * CH_ * CH_ * 3, y2, l);

        dim3 gl((lo + NTO - 1) / NTO, B_);
        k_legrec<<<gl, 256>>>(cur, lin_m + i * CH_ * MM_ * MM_,
                              filt_d, filt_r, y2, alt, l, lo);

        float* tmp = cur; cur = alt; alt = tmp;
        l = lo;
    }

    dim3 gf((LIN_ / 2 + 127) / 128, B_);
    k_final<<<gf, 128>>>(cur, w11, w_out, out, l);
}